// round 6
// baseline (speedup 1.0000x reference)
#include <cuda_runtime.h>
#include <math.h>

// FlowMatching: per-batch Gaussian blur (separable, K=9, sigma=0.1+0.9*t[b],
// dynamic radius mask r=ceil(4*sigma), zero padding) + lerp t*blur + (1-t)*x.
// x1: [128, 3, 512, 512] fp32, t: [128] fp32, out: same as x1.
//
// R5: restructure to cut L1 traffic ~2x (was the binding pipe at 79%):
//  - horizontal pass fused into the global load via warp shuffles (no s_in)
//  - TH=64 tile, vertical pass = 8-stacked rolling window (32B/quad reads)
//  - lerp's orig value reloaded from global (L1/L2 hit, no DRAM cost)
// smem = single 72x128 f32 h-filtered buffer (36.9 KB), one __syncthreads.

#define H 512
#define W 512
#define TW 128
#define TH 64
#define RAD 4
#define KS 9
#define HROWS (TH + 2 * RAD)           // 72
#define ROWS_PER_WARP (HROWS / 8)      // 9

__global__ __launch_bounds__(256, 3)
void flowmatch_blur_kernel(const float* __restrict__ x1,
                           const float* __restrict__ t,
                           float* __restrict__ out)
{
    __shared__ float s_h[HROWS][TW];   // 36864 B

    const int tid  = threadIdx.x;
    const int lane = tid & 31;
    const int warp = tid >> 5;
    const int plane = blockIdx.z;      // b*3 + c
    const int b  = plane / 3;
    const int x0 = blockIdx.x * TW;
    const int y0 = blockIdx.y * TH;

    const float tv = __ldg(&t[b]);

    // ---- normalized 1D gaussian weights, redundantly in every thread ----
    float w0,w1,w2,w3,w4,w5,w6,w7,w8;
    {
        float sigma  = __fadd_rn(0.1f, __fmul_rn(tv, 0.9f));
        float r      = ceilf(__fmul_rn(4.0f, sigma));
        float inv2s2 = 1.0f / (2.0f * sigma * sigma);
        float wl[KS];
        float sum = 0.0f;
        #pragma unroll
        for (int i = 0; i < KS; i++) {
            float c = (float)(i - RAD);
            float v = (fabsf(c) <= r) ? expf(-c * c * inv2s2) : 0.0f;
            wl[i] = v;
            sum += v;
        }
        float inv = 1.0f / sum;
        w0=wl[0]*inv; w1=wl[1]*inv; w2=wl[2]*inv; w3=wl[3]*inv; w4=wl[4]*inv;
        w5=wl[5]*inv; w6=wl[6]*inv; w7=wl[7]*inv; w8=wl[8]*inv;
    }

    const float* pin  = x1  + (size_t)plane * (H * W);
    float*       pout = out + (size_t)plane * (H * W);

    const unsigned FULL = 0xffffffffu;

    // ---- Phase H: load + horizontal 9-tap via shuffles, write s_h ----
    // warp w handles h-rows w*9 .. w*9+8; lane L handles quad L of the row.
    #pragma unroll
    for (int i = 0; i < ROWS_PER_WARP; i++) {
        int hr = warp * ROWS_PER_WARP + i;     // 0..71
        int gy = y0 - RAD + hr;
        bool gyok = (gy >= 0) && (gy < H);

        float4 v    = make_float4(0.f, 0.f, 0.f, 0.f);
        float4 halo = make_float4(0.f, 0.f, 0.f, 0.f);
        if (gyok) {
            v = *reinterpret_cast<const float4*>(pin + gy * W + x0 + lane * 4);
            if (lane == 0) {
                if (x0 > 0)
                    halo = *reinterpret_cast<const float4*>(pin + gy * W + x0 - 4);
            } else if (lane == 31) {
                if (x0 + TW < W)
                    halo = *reinterpret_cast<const float4*>(pin + gy * W + x0 + TW);
            }
        }

        float4 lq, rq;
        lq.x = __shfl_up_sync(FULL, v.x, 1);
        lq.y = __shfl_up_sync(FULL, v.y, 1);
        lq.z = __shfl_up_sync(FULL, v.z, 1);
        lq.w = __shfl_up_sync(FULL, v.w, 1);
        rq.x = __shfl_down_sync(FULL, v.x, 1);
        rq.y = __shfl_down_sync(FULL, v.y, 1);
        rq.z = __shfl_down_sync(FULL, v.z, 1);
        rq.w = __shfl_down_sync(FULL, v.w, 1);
        if (lane == 0)  lq = halo;   // left image/tile halo (zero-padded)
        if (lane == 31) rq = halo;   // right halo

        float f0=lq.x, f1=lq.y, f2=lq.z, f3=lq.w;
        float f4=v.x,  f5=v.y,  f6=v.z,  f7=v.w;
        float f8=rq.x, f9=rq.y, f10=rq.z, f11=rq.w;

        float4 o;
        o.x = w0*f0 + w1*f1 + w2*f2 + w3*f3 + w4*f4 + w5*f5 + w6*f6 + w7*f7 + w8*f8;
        o.y = w0*f1 + w1*f2 + w2*f3 + w3*f4 + w4*f5 + w5*f6 + w6*f7 + w7*f8 + w8*f9;
        o.z = w0*f2 + w1*f3 + w2*f4 + w3*f5 + w4*f6 + w5*f7 + w6*f8 + w7*f9 + w8*f10;
        o.w = w0*f3 + w1*f4 + w2*f5 + w3*f6 + w4*f7 + w5*f8 + w6*f9 + w7*f10 + w8*f11;

        *reinterpret_cast<float4*>(&s_h[hr][lane * 4]) = o;
    }

    __syncthreads();

    // ---- Phase V: vertical 9-tap over 8 stacked outputs + lerp ----
    // warp = y-group (8 outputs), lane = x-quad. h-row hr feeds output y with
    // weight w[hr - y] (hr = y..y+8 in local h-row coords).
    {
        const int xq    = lane * 4;
        const int ybase = warp * 8;          // 0,8,...,56
        const float omt = 1.0f - tv;
        const float wt[KS] = {w0,w1,w2,w3,w4,w5,w6,w7,w8};

        float4 acc[8];
        #pragma unroll
        for (int j = 0; j < 8; j++) acc[j] = make_float4(0.f, 0.f, 0.f, 0.f);

        #pragma unroll
        for (int r = 0; r < 16; r++) {
            float4 hv = *reinterpret_cast<const float4*>(&s_h[ybase + r][xq]);
            #pragma unroll
            for (int j = 0; j < 8; j++) {
                int k = r - j;
                if (k >= 0 && k < KS) {
                    float wd = wt[k];
                    acc[j].x += wd * hv.x;
                    acc[j].y += wd * hv.y;
                    acc[j].z += wd * hv.z;
                    acc[j].w += wd * hv.w;
                }
            }
        }

        #pragma unroll
        for (int j = 0; j < 8; j++) {
            int gy = y0 + ybase + j;
            float4 orig = *reinterpret_cast<const float4*>(pin + gy * W + x0 + xq);
            float4 o;
            o.x = tv * acc[j].x + omt * orig.x;
            o.y = tv * acc[j].y + omt * orig.y;
            o.z = tv * acc[j].z + omt * orig.z;
            o.w = tv * acc[j].w + omt * orig.w;
            *reinterpret_cast<float4*>(pout + gy * W + x0 + xq) = o;
        }
    }
}

extern "C" void kernel_launch(void* const* d_in, const int* in_sizes, int n_in,
                              void* d_out, int out_size)
{
    const float* x1 = (const float*)d_in[0];
    const float* t  = (const float*)d_in[1];
    float* out      = (float*)d_out;

    dim3 grid(W / TW, H / TH, 384);   // 4 x 8 x 384 = 12288 blocks
    dim3 block(256);
    flowmatch_blur_kernel<<<grid, block>>>(x1, t, out);
}

// round 7
// speedup vs baseline: 1.5155x; 1.5155x over previous
#include <cuda_runtime.h>
#include <math.h>

// FlowMatching: per-batch Gaussian blur (separable, K=9, sigma=0.1+0.9*t[b],
// dynamic radius mask r=ceil(4*sigma), zero padding) + lerp t*blur + (1-t)*x.
// x1: [128, 3, 512, 512] fp32, t: [128] fp32, out: same as x1.
//
// R6: R4 structure minus s_in. Horizontal pass reads global directly with
// 3 overlapping aligned LDG.128 (L1 hits for the overlap), writes only the
// h-filtered tile to smem. Vertical pass = R4's 12-row rolling window;
// lerp orig reloaded from global (L1-resident). 20.5 KB smem, 1 sync.

#define H 512
#define W 512
#define TW 128
#define TH 32
#define RAD 4
#define KS 9
#define HROWS (TH + 2 * RAD)   // 40

__global__ __launch_bounds__(256, 4)
void flowmatch_blur_kernel(const float* __restrict__ x1,
                           const float* __restrict__ t,
                           float* __restrict__ out)
{
    __shared__ float s_h[HROWS][TW];   // 40*128*4 = 20480 B

    const int tid   = threadIdx.x;
    const int plane = blockIdx.z;      // b*3 + c, 384 planes
    const int b     = plane / 3;
    const int x0    = blockIdx.x * TW;
    const int y0    = blockIdx.y * TH;

    const float tv = __ldg(&t[b]);

    // ---- normalized 1D gaussian weights, per-thread in registers ----
    float w0,w1,w2,w3,w4,w5,w6,w7,w8;
    {
        float sigma  = __fadd_rn(0.1f, __fmul_rn(tv, 0.9f));
        float r      = ceilf(__fmul_rn(4.0f, sigma));
        float inv2s2 = 1.0f / (2.0f * sigma * sigma);
        float wl[KS];
        float sum = 0.0f;
        #pragma unroll
        for (int i = 0; i < KS; i++) {
            float c = (float)(i - RAD);
            float v = (fabsf(c) <= r) ? expf(-c * c * inv2s2) : 0.0f;
            wl[i] = v;
            sum += v;
        }
        float inv = 1.0f / sum;
        w0=wl[0]*inv; w1=wl[1]*inv; w2=wl[2]*inv; w3=wl[3]*inv; w4=wl[4]*inv;
        w5=wl[5]*inv; w6=wl[6]*inv; w7=wl[7]*inv; w8=wl[8]*inv;
    }

    const float* pin  = x1  + (size_t)plane * (H * W);
    float*       pout = out + (size_t)plane * (H * W);

    // ---- Phase H: 3 overlapping LDG.128 -> horizontal 9-tap -> STS.128 ----
    // 40 rows x 32 quads = 1280 items, 5 per thread.
    #pragma unroll
    for (int it = 0; it < 5; it++) {
        int idx = tid + it * 256;       // 0..1279
        int row = idx >> 5;             // 0..39
        int q   = idx & 31;             // 0..31
        int gy  = y0 - RAD + row;
        int gx  = x0 + q * 4;           // output quad global x (16B aligned)

        float4 A  = make_float4(0.f, 0.f, 0.f, 0.f);  // [gx-4, gx)
        float4 Bv = make_float4(0.f, 0.f, 0.f, 0.f);  // [gx,   gx+4)
        float4 Cv = make_float4(0.f, 0.f, 0.f, 0.f);  // [gx+4, gx+8)
        if (gy >= 0 && gy < H) {
            const float* rp = pin + gy * W + gx;
            if (gx > 0)
                A = *reinterpret_cast<const float4*>(rp - 4);
            Bv = *reinterpret_cast<const float4*>(rp);
            if (gx + 4 < W)
                Cv = *reinterpret_cast<const float4*>(rp + 4);
        }

        float f0=A.x,  f1=A.y,  f2=A.z,  f3=A.w;
        float f4=Bv.x, f5=Bv.y, f6=Bv.z, f7=Bv.w;
        float f8=Cv.x, f9=Cv.y, f10=Cv.z, f11=Cv.w;

        float4 o;
        o.x = w0*f0 + w1*f1 + w2*f2 + w3*f3 + w4*f4 + w5*f5 + w6*f6 + w7*f7 + w8*f8;
        o.y = w0*f1 + w1*f2 + w2*f3 + w3*f4 + w4*f5 + w5*f6 + w6*f7 + w7*f8 + w8*f9;
        o.z = w0*f2 + w1*f3 + w2*f4 + w3*f5 + w4*f6 + w5*f7 + w6*f8 + w7*f9 + w8*f10;
        o.w = w0*f3 + w1*f4 + w2*f5 + w3*f6 + w4*f7 + w5*f8 + w6*f9 + w7*f10 + w8*f11;

        *reinterpret_cast<float4*>(&s_h[row][q * 4]) = o;
    }

    __syncthreads();

    // ---- Phase V: vertical 9-tap, rolling 12-row window, 4 stacked quads,
    //      lerp with orig reloaded from global (L1-resident) ----
    {
        const int xq    = (tid & 31) * 4;
        const int ybase = (tid >> 5) * 4;   // 0,4,...,28
        const float omt = 1.0f - tv;

        float4 acc0 = make_float4(0.f,0.f,0.f,0.f);
        float4 acc1 = make_float4(0.f,0.f,0.f,0.f);
        float4 acc2 = make_float4(0.f,0.f,0.f,0.f);
        float4 acc3 = make_float4(0.f,0.f,0.f,0.f);
        const float wt[KS] = {w0,w1,w2,w3,w4,w5,w6,w7,w8};

        // rows ybase..ybase+11 of s_h feed outputs ybase..ybase+3
        #pragma unroll
        for (int r = 0; r < 12; r++) {
            float4 hv = *reinterpret_cast<const float4*>(&s_h[ybase + r][xq]);
            if (r <= 8) {
                float wd = wt[r];
                acc0.x += wd * hv.x; acc0.y += wd * hv.y;
                acc0.z += wd * hv.z; acc0.w += wd * hv.w;
            }
            if (r >= 1 && r <= 9) {
                float wd = wt[r - 1];
                acc1.x += wd * hv.x; acc1.y += wd * hv.y;
                acc1.z += wd * hv.z; acc1.w += wd * hv.w;
            }
            if (r >= 2 && r <= 10) {
                float wd = wt[r - 2];
                acc2.x += wd * hv.x; acc2.y += wd * hv.y;
                acc2.z += wd * hv.z; acc2.w += wd * hv.w;
            }
            if (r >= 3) {                    // r max 11 -> weight idx max 8
                float wd = wt[r - 3];
                acc3.x += wd * hv.x; acc3.y += wd * hv.y;
                acc3.z += wd * hv.z; acc3.w += wd * hv.w;
            }
        }

        #pragma unroll
        for (int j = 0; j < 4; j++) {
            float4 acc = (j == 0) ? acc0 : (j == 1) ? acc1 : (j == 2) ? acc2 : acc3;
            int gy = y0 + ybase + j;
            float4 orig = *reinterpret_cast<const float4*>(pin + gy * W + x0 + xq);
            float4 o;
            o.x = tv * acc.x + omt * orig.x;
            o.y = tv * acc.y + omt * orig.y;
            o.z = tv * acc.z + omt * orig.z;
            o.w = tv * acc.w + omt * orig.w;
            *reinterpret_cast<float4*>(pout + gy * W + x0 + xq) = o;
        }
    }
}

extern "C" void kernel_launch(void* const* d_in, const int* in_sizes, int n_in,
                              void* d_out, int out_size)
{
    const float* x1 = (const float*)d_in[0];
    const float* t  = (const float*)d_in[1];
    float* out      = (float*)d_out;

    dim3 grid(W / TW, H / TH, 384);   // 4 x 16 x 384 = 24576 blocks
    dim3 block(256);
    flowmatch_blur_kernel<<<grid, block>>>(x1, t, out);
}

// round 8
// speedup vs baseline: 1.9061x; 1.2578x over previous
#include <cuda_runtime.h>
#include <cuda_fp16.h>
#include <math.h>

// FlowMatching: per-batch Gaussian blur (separable, K=9, sigma=0.1+0.9*t[b],
// dynamic radius mask r=ceil(4*sigma), zero padding) + lerp t*blur + (1-t)*x.
// x1: [128, 3, 512, 512] fp32, t: [128] fp32, out: same as x1.
//
// R7: R6 topology (h-filter straight from global, no s_in) with two fixes:
//  - s_h stored fp16 (compute fp32, one rounding; tol is 1e-3) -> L1 bytes -37%
//  - launch_bounds(256,3): 85-reg cap so ptxas can hoist the 15 phase-H
//    loads (R6's 64-reg cap serialized them -> latency-bound at 229us).

#define H 512
#define W 512
#define TW 128
#define TH 32
#define RAD 4
#define KS 9
#define HROWS (TH + 2 * RAD)   // 40

__global__ __launch_bounds__(256, 3)
void flowmatch_blur_kernel(const float* __restrict__ x1,
                           const float* __restrict__ t,
                           float* __restrict__ out)
{
    __shared__ __align__(16) __half s_h[HROWS][TW];   // 40*128*2 = 10240 B

    const int tid   = threadIdx.x;
    const int plane = blockIdx.z;      // b*3 + c, 384 planes
    const int b     = plane / 3;
    const int x0    = blockIdx.x * TW;
    const int y0    = blockIdx.y * TH;

    const float tv = __ldg(&t[b]);

    // ---- normalized 1D gaussian weights, per-thread in registers ----
    float w0,w1,w2,w3,w4,w5,w6,w7,w8;
    {
        float sigma  = __fadd_rn(0.1f, __fmul_rn(tv, 0.9f));
        float r      = ceilf(__fmul_rn(4.0f, sigma));
        float inv2s2 = 1.0f / (2.0f * sigma * sigma);
        float wl[KS];
        float sum = 0.0f;
        #pragma unroll
        for (int i = 0; i < KS; i++) {
            float c = (float)(i - RAD);
            float v = (fabsf(c) <= r) ? expf(-c * c * inv2s2) : 0.0f;
            wl[i] = v;
            sum += v;
        }
        float inv = 1.0f / sum;
        w0=wl[0]*inv; w1=wl[1]*inv; w2=wl[2]*inv; w3=wl[3]*inv; w4=wl[4]*inv;
        w5=wl[5]*inv; w6=wl[6]*inv; w7=wl[7]*inv; w8=wl[8]*inv;
    }

    const float* pin  = x1  + (size_t)plane * (H * W);
    float*       pout = out + (size_t)plane * (H * W);

    // ---- Phase H: load all 15 float4 up front (max MLP), then filter ----
    // 40 rows x 32 quads = 1280 items, 5 per thread.
    float4 Av[5], Bv[5], Cv[5];
    #pragma unroll
    for (int it = 0; it < 5; it++) {
        int idx = tid + it * 256;
        int row = idx >> 5;
        int q   = idx & 31;
        int gy  = y0 - RAD + row;
        int gx  = x0 + q * 4;

        Av[it] = make_float4(0.f, 0.f, 0.f, 0.f);
        Bv[it] = make_float4(0.f, 0.f, 0.f, 0.f);
        Cv[it] = make_float4(0.f, 0.f, 0.f, 0.f);
        if (gy >= 0 && gy < H) {
            const float* rp = pin + gy * W + gx;
            if (gx > 0)
                Av[it] = *reinterpret_cast<const float4*>(rp - 4);
            Bv[it] = *reinterpret_cast<const float4*>(rp);
            if (gx + 4 < W)
                Cv[it] = *reinterpret_cast<const float4*>(rp + 4);
        }
    }

    #pragma unroll
    for (int it = 0; it < 5; it++) {
        int idx = tid + it * 256;
        int row = idx >> 5;
        int q   = idx & 31;

        float f0=Av[it].x, f1=Av[it].y, f2=Av[it].z,  f3=Av[it].w;
        float f4=Bv[it].x, f5=Bv[it].y, f6=Bv[it].z,  f7=Bv[it].w;
        float f8=Cv[it].x, f9=Cv[it].y, f10=Cv[it].z, f11=Cv[it].w;

        float4 o;
        o.x = w0*f0 + w1*f1 + w2*f2 + w3*f3 + w4*f4 + w5*f5 + w6*f6 + w7*f7 + w8*f8;
        o.y = w0*f1 + w1*f2 + w2*f3 + w3*f4 + w4*f5 + w5*f6 + w6*f7 + w7*f8 + w8*f9;
        o.z = w0*f2 + w1*f3 + w2*f4 + w3*f5 + w4*f6 + w5*f7 + w6*f8 + w7*f9 + w8*f10;
        o.w = w0*f3 + w1*f4 + w2*f5 + w3*f6 + w4*f7 + w5*f8 + w6*f9 + w7*f10 + w8*f11;

        // round once to fp16 and store 8 bytes
        __half2 h01 = __floats2half2_rn(o.x, o.y);
        __half2 h23 = __floats2half2_rn(o.z, o.w);
        uint2 packed;
        packed.x = *reinterpret_cast<unsigned*>(&h01);
        packed.y = *reinterpret_cast<unsigned*>(&h23);
        *reinterpret_cast<uint2*>(&s_h[row][q * 4]) = packed;
    }

    __syncthreads();

    // ---- Phase V: vertical 9-tap (fp32 accum from fp16 rows), rolling
    //      12-row window, 4 stacked quads; lerp orig reloaded from global ----
    {
        const int xq    = (tid & 31) * 4;
        const int ybase = (tid >> 5) * 4;   // 0,4,...,28
        const float omt = 1.0f - tv;
        const float wt[KS] = {w0,w1,w2,w3,w4,w5,w6,w7,w8};

        float4 acc0 = make_float4(0.f,0.f,0.f,0.f);
        float4 acc1 = make_float4(0.f,0.f,0.f,0.f);
        float4 acc2 = make_float4(0.f,0.f,0.f,0.f);
        float4 acc3 = make_float4(0.f,0.f,0.f,0.f);

        #pragma unroll
        for (int r = 0; r < 12; r++) {
            uint2 raw = *reinterpret_cast<const uint2*>(&s_h[ybase + r][xq]);
            __half2 h01 = *reinterpret_cast<__half2*>(&raw.x);
            __half2 h23 = *reinterpret_cast<__half2*>(&raw.y);
            float2 lo = __half22float2(h01);
            float2 hi = __half22float2(h23);
            float hx = lo.x, hy = lo.y, hz = hi.x, hw = hi.y;

            if (r <= 8) {
                float wd = wt[r];
                acc0.x += wd * hx; acc0.y += wd * hy;
                acc0.z += wd * hz; acc0.w += wd * hw;
            }
            if (r >= 1 && r <= 9) {
                float wd = wt[r - 1];
                acc1.x += wd * hx; acc1.y += wd * hy;
                acc1.z += wd * hz; acc1.w += wd * hw;
            }
            if (r >= 2 && r <= 10) {
                float wd = wt[r - 2];
                acc2.x += wd * hx; acc2.y += wd * hy;
                acc2.z += wd * hz; acc2.w += wd * hw;
            }
            if (r >= 3) {                    // r max 11 -> weight idx max 8
                float wd = wt[r - 3];
                acc3.x += wd * hx; acc3.y += wd * hy;
                acc3.z += wd * hz; acc3.w += wd * hw;
            }
        }

        #pragma unroll
        for (int j = 0; j < 4; j++) {
            float4 acc = (j == 0) ? acc0 : (j == 1) ? acc1 : (j == 2) ? acc2 : acc3;
            int gy = y0 + ybase + j;
            float4 orig = *reinterpret_cast<const float4*>(pin + gy * W + x0 + xq);
            float4 o;
            o.x = tv * acc.x + omt * orig.x;
            o.y = tv * acc.y + omt * orig.y;
            o.z = tv * acc.z + omt * orig.z;
            o.w = tv * acc.w + omt * orig.w;
            *reinterpret_cast<float4*>(pout + gy * W + x0 + xq) = o;
        }
    }
}

extern "C" void kernel_launch(void* const* d_in, const int* in_sizes, int n_in,
                              void* d_out, int out_size)
{
    const float* x1 = (const float*)d_in[0];
    const float* t  = (const float*)d_in[1];
    float* out      = (float*)d_out;

    dim3 grid(W / TW, H / TH, 384);   // 4 x 16 x 384 = 24576 blocks
    dim3 block(256);
    flowmatch_blur_kernel<<<grid, block>>>(x1, t, out);
}

// round 9
// speedup vs baseline: 2.0022x; 1.0504x over previous
#include <cuda_runtime.h>
#include <cuda_fp16.h>
#include <math.h>

// FlowMatching: per-batch Gaussian blur (separable, K=9, sigma=0.1+0.9*t[b],
// dynamic radius mask r=ceil(4*sigma), zero padding) + lerp t*blur + (1-t)*x.
// x1: [128, 3, 512, 512] fp32, t: [128] fp32, out: same as x1.
//
// R8: R7 + packed fp32x2 FMA (FFMA2, PTX-only on sm_103a) in the vertical
// pass: 144 scalar FFMA -> 72 FFMA2. Kernel was issue-bound (74.7%) with
// fma pipe at 46%; this halves the dominant FMA stream at identical fp32
// precision. Phase H left scalar (sliding window breaks pair alignment).

#define H 512
#define W 512
#define TW 128
#define TH 32
#define RAD 4
#define KS 9
#define HROWS (TH + 2 * RAD)   // 40

typedef unsigned long long u64;

__device__ __forceinline__ u64 packf2(float lo, float hi) {
    u64 r;
    asm("mov.b64 %0, {%1, %2};" : "=l"(r) : "f"(lo), "f"(hi));
    return r;
}
__device__ __forceinline__ u64 ffma2(u64 a, u64 b, u64 c) {
    u64 d;
    asm("fma.rn.f32x2 %0, %1, %2, %3;" : "=l"(d) : "l"(a), "l"(b), "l"(c));
    return d;
}
__device__ __forceinline__ void unpackf2(u64 v, float& lo, float& hi) {
    asm("mov.b64 {%0, %1}, %2;" : "=f"(lo), "=f"(hi) : "l"(v));
}

__global__ __launch_bounds__(256, 3)
void flowmatch_blur_kernel(const float* __restrict__ x1,
                           const float* __restrict__ t,
                           float* __restrict__ out)
{
    __shared__ __align__(16) __half s_h[HROWS][TW];   // 10240 B

    const int tid   = threadIdx.x;
    const int plane = blockIdx.z;      // b*3 + c, 384 planes
    const int b     = plane / 3;
    const int x0    = blockIdx.x * TW;
    const int y0    = blockIdx.y * TH;

    const float tv = __ldg(&t[b]);

    // ---- normalized 1D gaussian weights, per-thread in registers ----
    float w0,w1,w2,w3,w4,w5,w6,w7,w8;
    {
        float sigma  = __fadd_rn(0.1f, __fmul_rn(tv, 0.9f));
        float r      = ceilf(__fmul_rn(4.0f, sigma));
        float inv2s2 = 1.0f / (2.0f * sigma * sigma);
        float wl[KS];
        float sum = 0.0f;
        #pragma unroll
        for (int i = 0; i < KS; i++) {
            float c = (float)(i - RAD);
            float v = (fabsf(c) <= r) ? expf(-c * c * inv2s2) : 0.0f;
            wl[i] = v;
            sum += v;
        }
        float inv = 1.0f / sum;
        w0=wl[0]*inv; w1=wl[1]*inv; w2=wl[2]*inv; w3=wl[3]*inv; w4=wl[4]*inv;
        w5=wl[5]*inv; w6=wl[6]*inv; w7=wl[7]*inv; w8=wl[8]*inv;
    }

    const float* pin  = x1  + (size_t)plane * (H * W);
    float*       pout = out + (size_t)plane * (H * W);

    // ---- Phase H: hoist all 15 float4 loads (MLP), filter, store fp16 ----
    float4 Av[5], Bv[5], Cv[5];
    #pragma unroll
    for (int it = 0; it < 5; it++) {
        int idx = tid + it * 256;
        int row = idx >> 5;
        int q   = idx & 31;
        int gy  = y0 - RAD + row;
        int gx  = x0 + q * 4;

        Av[it] = make_float4(0.f, 0.f, 0.f, 0.f);
        Bv[it] = make_float4(0.f, 0.f, 0.f, 0.f);
        Cv[it] = make_float4(0.f, 0.f, 0.f, 0.f);
        if (gy >= 0 && gy < H) {
            const float* rp = pin + gy * W + gx;
            if (gx > 0)
                Av[it] = *reinterpret_cast<const float4*>(rp - 4);
            Bv[it] = *reinterpret_cast<const float4*>(rp);
            if (gx + 4 < W)
                Cv[it] = *reinterpret_cast<const float4*>(rp + 4);
        }
    }

    #pragma unroll
    for (int it = 0; it < 5; it++) {
        int idx = tid + it * 256;
        int row = idx >> 5;
        int q   = idx & 31;

        float f0=Av[it].x, f1=Av[it].y, f2=Av[it].z,  f3=Av[it].w;
        float f4=Bv[it].x, f5=Bv[it].y, f6=Bv[it].z,  f7=Bv[it].w;
        float f8=Cv[it].x, f9=Cv[it].y, f10=Cv[it].z, f11=Cv[it].w;

        float4 o;
        o.x = w0*f0 + w1*f1 + w2*f2 + w3*f3 + w4*f4 + w5*f5 + w6*f6 + w7*f7 + w8*f8;
        o.y = w0*f1 + w1*f2 + w2*f3 + w3*f4 + w4*f5 + w5*f6 + w6*f7 + w7*f8 + w8*f9;
        o.z = w0*f2 + w1*f3 + w2*f4 + w3*f5 + w4*f6 + w5*f7 + w6*f8 + w7*f9 + w8*f10;
        o.w = w0*f3 + w1*f4 + w2*f5 + w3*f6 + w4*f7 + w5*f8 + w6*f9 + w7*f10 + w8*f11;

        __half2 h01 = __floats2half2_rn(o.x, o.y);
        __half2 h23 = __floats2half2_rn(o.z, o.w);
        uint2 packed;
        packed.x = *reinterpret_cast<unsigned*>(&h01);
        packed.y = *reinterpret_cast<unsigned*>(&h23);
        *reinterpret_cast<uint2*>(&s_h[row][q * 4]) = packed;
    }

    __syncthreads();

    // ---- Phase V: vertical 9-tap with FFMA2, rolling 12-row window,
    //      4 stacked quads; lerp with orig reloaded from global ----
    {
        const int xq    = (tid & 31) * 4;
        const int ybase = (tid >> 5) * 4;   // 0,4,...,28
        const float omt = 1.0f - tv;

        // duplicated weight pairs for packed FMA
        u64 wp[KS];
        wp[0]=packf2(w0,w0); wp[1]=packf2(w1,w1); wp[2]=packf2(w2,w2);
        wp[3]=packf2(w3,w3); wp[4]=packf2(w4,w4); wp[5]=packf2(w5,w5);
        wp[6]=packf2(w6,w6); wp[7]=packf2(w7,w7); wp[8]=packf2(w8,w8);

        u64 a0lo=0, a0hi=0, a1lo=0, a1hi=0,
            a2lo=0, a2hi=0, a3lo=0, a3hi=0;   // (0ull == packed {0.f,0.f})

        #pragma unroll
        for (int r = 0; r < 12; r++) {
            uint2 raw = *reinterpret_cast<const uint2*>(&s_h[ybase + r][xq]);
            __half2 h01 = *reinterpret_cast<__half2*>(&raw.x);
            __half2 h23 = *reinterpret_cast<__half2*>(&raw.y);
            float2 lo = __half22float2(h01);
            float2 hi = __half22float2(h23);
            u64 plo = packf2(lo.x, lo.y);
            u64 phi = packf2(hi.x, hi.y);

            if (r <= 8) {
                a0lo = ffma2(wp[r], plo, a0lo);
                a0hi = ffma2(wp[r], phi, a0hi);
            }
            if (r >= 1 && r <= 9) {
                a1lo = ffma2(wp[r-1], plo, a1lo);
                a1hi = ffma2(wp[r-1], phi, a1hi);
            }
            if (r >= 2 && r <= 10) {
                a2lo = ffma2(wp[r-2], plo, a2lo);
                a2hi = ffma2(wp[r-2], phi, a2hi);
            }
            if (r >= 3) {                      // r max 11 -> weight idx max 8
                a3lo = ffma2(wp[r-3], plo, a3lo);
                a3hi = ffma2(wp[r-3], phi, a3hi);
            }
        }

        u64 alo[4] = {a0lo, a1lo, a2lo, a3lo};
        u64 ahi[4] = {a0hi, a1hi, a2hi, a3hi};

        #pragma unroll
        for (int j = 0; j < 4; j++) {
            float ax, ay, az, aw;
            unpackf2(alo[j], ax, ay);
            unpackf2(ahi[j], az, aw);

            int gy = y0 + ybase + j;
            float4 orig = *reinterpret_cast<const float4*>(pin + gy * W + x0 + xq);
            float4 o;
            o.x = tv * ax + omt * orig.x;
            o.y = tv * ay + omt * orig.y;
            o.z = tv * az + omt * orig.z;
            o.w = tv * aw + omt * orig.w;
            *reinterpret_cast<float4*>(pout + gy * W + x0 + xq) = o;
        }
    }
}

extern "C" void kernel_launch(void* const* d_in, const int* in_sizes, int n_in,
                              void* d_out, int out_size)
{
    const float* x1 = (const float*)d_in[0];
    const float* t  = (const float*)d_in[1];
    float* out      = (float*)d_out;

    dim3 grid(W / TW, H / TH, 384);   // 4 x 16 x 384 = 24576 blocks
    dim3 block(256);
    flowmatch_blur_kernel<<<grid, block>>>(x1, t, out);
}